// round 5
// baseline (speedup 1.0000x reference)
#include <cuda_runtime.h>

#define BB 64
#define TT 2048
#define DD 512

// Scratch (allocation-free contract: __device__ globals)
__device__ float g_phis[BB * DD];
__device__ float g_v[BB * DD];
__device__ float g_e[BB * TT];
__device__ float g_hsum[BB * TT];
__device__ float g_M[BB];
__device__ float g_invS[BB];

// ---------------------------------------------------------------------------
// k_phis: phi_s[b,a] = dot(s[b,:], phi_w[a,:]) + phi_b[a]
// grid (32 a-tiles, 64 b) = 2048 blocks x 256 threads. Each warp does 2 a's.
// ---------------------------------------------------------------------------
__global__ void k_phis(const float* __restrict__ s,
                       const float* __restrict__ phi_w,
                       const float* __restrict__ phi_b) {
    const int b    = blockIdx.y;
    const int tid  = threadIdx.x;          // 256
    const int lane = tid & 31;
    const int warp = tid >> 5;             // 8 warps

    __shared__ float sh_s[DD];
    sh_s[tid]       = s[(size_t)b * DD + tid];
    sh_s[tid + 256] = s[(size_t)b * DD + tid + 256];
    __syncthreads();
    const float4* s4 = (const float4*)sh_s;

    const int a0 = blockIdx.x * 16 + warp * 2;
    const int a1 = a0 + 1;
    const float4* w0 = (const float4*)(phi_w + (size_t)a0 * DD);
    const float4* w1 = (const float4*)(phi_w + (size_t)a1 * DD);

    float acc0 = 0.f, acc1 = 0.f;
    #pragma unroll
    for (int j = 0; j < 4; j++) {
        float4 wa = w0[lane + 32 * j];
        float4 wb = w1[lane + 32 * j];
        float4 sv = s4[lane + 32 * j];
        acc0 += wa.x * sv.x + wa.y * sv.y + wa.z * sv.z + wa.w * sv.w;
        acc1 += wb.x * sv.x + wb.y * sv.y + wb.z * sv.z + wb.w * sv.w;
    }
    #pragma unroll
    for (int off = 16; off; off >>= 1) {
        acc0 += __shfl_xor_sync(0xffffffffu, acc0, off);
        acc1 += __shfl_xor_sync(0xffffffffu, acc1, off);
    }
    if (lane == 0) {
        g_phis[b * DD + a0] = acc0 + phi_b[a0];
        g_phis[b * DD + a1] = acc1 + phi_b[a1];
    }
}

// ---------------------------------------------------------------------------
// k_v: v[b,k] = sum_a phi_s[b,a] * psi_w[a,k]
// grid (32 b-pairs, 4 k-slices) = 128 blocks x 512 threads (16 warps).
// psi_b dropped: softmax is shift-invariant to the per-b constant it adds.
// ---------------------------------------------------------------------------
__global__ void k_v(const float* __restrict__ psi_w) {
    const int b0   = blockIdx.x * 2;
    const int ks   = blockIdx.y;           // k-slice: 32 float4 columns
    const int tid  = threadIdx.x;          // 512
    const int lane = tid & 31;
    const int warp = tid >> 5;             // 16 warps

    __shared__ float  ph0[DD], ph1[DD];
    __shared__ float4 part0[16][32];
    __shared__ float4 part1[16][32];

    ph0[tid] = g_phis[(size_t)b0 * DD + tid];
    ph1[tid] = g_phis[(size_t)(b0 + 1) * DD + tid];
    __syncthreads();

    const float4* w4 = (const float4*)psi_w;     // [512][128] float4
    const int col = ks * 32 + lane;              // 0..127

    float4 acc0 = make_float4(0.f, 0.f, 0.f, 0.f);
    float4 acc1 = make_float4(0.f, 0.f, 0.f, 0.f);
    const int abase = warp * 32;
    #pragma unroll 8
    for (int i = 0; i < 32; i++) {
        const int a = abase + i;
        const float4 w = w4[(size_t)a * 128 + col];
        const float p0 = ph0[a], p1 = ph1[a];
        acc0.x += p0 * w.x; acc0.y += p0 * w.y;
        acc0.z += p0 * w.z; acc0.w += p0 * w.w;
        acc1.x += p1 * w.x; acc1.y += p1 * w.y;
        acc1.z += p1 * w.z; acc1.w += p1 * w.w;
    }
    part0[warp][lane] = acc0;
    part1[warp][lane] = acc1;
    __syncthreads();

    if (warp == 0) {
        float4 r = part0[0][lane];
        #pragma unroll
        for (int w = 1; w < 16; w++) {
            float4 p = part0[w][lane];
            r.x += p.x; r.y += p.y; r.z += p.z; r.w += p.w;
        }
        ((float4*)g_v)[(size_t)b0 * 128 + col] = r;
    } else if (warp == 1) {
        float4 r = part1[0][lane];
        #pragma unroll
        for (int w = 1; w < 16; w++) {
            float4 p = part1[w][lane];
            r.x += p.x; r.y += p.y; r.z += p.z; r.w += p.w;
        }
        ((float4*)g_v)[(size_t)(b0 + 1) * 128 + col] = r;
    }
}

// ---------------------------------------------------------------------------
// k_scores: THE DRAM-bound pass (one 268 MB streaming read of h).
// grid 1024 x 256: 8192 warps; warp w owns 16 CONSECUTIVE rows
// [16w, 16w+16) -- all in the same b (2048 % 16 == 0), so v is loaded
// into 16 registers exactly once per warp and reused across 4 quads.
// Each quad: 16 independent LDG.128/lane, dot + row-sum, 2 float4 stores.
// Looping (vs one-shot blocks) amortizes CTA start/stop, cuts waves
// 14 -> ~3.5, and staggers load batches across warps.
// ---------------------------------------------------------------------------
__global__ void k_scores(const float* __restrict__ h) {
    const int lane  = threadIdx.x & 31;
    const int warp  = threadIdx.x >> 5;
    const int wglob = blockIdx.x * 8 + warp;     // 0..8191
    const int rbase = wglob * 16;
    const int b     = rbase >> 11;               // same for all 16 rows

    const float4* v4 = (const float4*)(g_v + (size_t)b * DD);
    float4 v[4];
    #pragma unroll
    for (int j = 0; j < 4; j++) v[j] = v4[lane + 32 * j];

    #pragma unroll 1
    for (int q = 0; q < 4; q++) {
        const int row0 = rbase + q * 4;
        const float4* hp = (const float4*)(h + (size_t)row0 * DD);

        float4 A[4][4];
        #pragma unroll
        for (int r = 0; r < 4; r++)
            #pragma unroll
            for (int j = 0; j < 4; j++)
                A[r][j] = hp[r * 128 + lane + 32 * j];

        float e[4], hs[4];
        #pragma unroll
        for (int r = 0; r < 4; r++) {
            float ee = 0.f, ss = 0.f;
            #pragma unroll
            for (int j = 0; j < 4; j++) {
                ee += A[r][j].x * v[j].x + A[r][j].y * v[j].y
                    + A[r][j].z * v[j].z + A[r][j].w * v[j].w;
                ss += (A[r][j].x + A[r][j].y) + (A[r][j].z + A[r][j].w);
            }
            e[r] = ee; hs[r] = ss;
        }
        #pragma unroll
        for (int off = 16; off; off >>= 1) {
            #pragma unroll
            for (int r = 0; r < 4; r++) {
                e[r]  += __shfl_xor_sync(0xffffffffu, e[r],  off);
                hs[r] += __shfl_xor_sync(0xffffffffu, hs[r], off);
            }
        }
        if (lane == 0) {
            *(float4*)(g_e    + row0) = make_float4(e[0],  e[1],  e[2],  e[3]);
            *(float4*)(g_hsum + row0) = make_float4(hs[0], hs[1], hs[2], hs[3]);
        }
    }
}

// ---------------------------------------------------------------------------
// k_red: per-b M = max_t e[b,t]; invS = 1/sum_t exp(e-M). Reads only g_e
// (512 KB, L2-hot). 64 blocks x 256 threads, 8 e/thread.
// ---------------------------------------------------------------------------
__global__ void k_red() {
    const int b    = blockIdx.x;
    const int tid  = threadIdx.x;          // 256
    const int lane = tid & 31;
    const int warp = tid >> 5;             // 8 warps
    __shared__ float red[8];

    const float4* e4 = (const float4*)(g_e + (size_t)b * TT);
    const float4 e0 = e4[tid];
    const float4 e1 = e4[tid + 256];

    float m = fmaxf(fmaxf(fmaxf(e0.x, e0.y), fmaxf(e0.z, e0.w)),
                    fmaxf(fmaxf(e1.x, e1.y), fmaxf(e1.z, e1.w)));
    #pragma unroll
    for (int off = 16; off; off >>= 1)
        m = fmaxf(m, __shfl_xor_sync(0xffffffffu, m, off));
    if (lane == 0) red[warp] = m;
    __syncthreads();
    float M = red[0];
    #pragma unroll
    for (int w = 1; w < 8; w++) M = fmaxf(M, red[w]);
    __syncthreads();

    float sum = __expf(e0.x - M) + __expf(e0.y - M)
              + __expf(e0.z - M) + __expf(e0.w - M)
              + __expf(e1.x - M) + __expf(e1.y - M)
              + __expf(e1.z - M) + __expf(e1.w - M);
    #pragma unroll
    for (int off = 16; off; off >>= 1)
        sum += __shfl_xor_sync(0xffffffffu, sum, off);
    if (lane == 0) red[warp] = sum;
    __syncthreads();
    if (tid == 0) {
        float S = 0.f;
        #pragma unroll
        for (int w = 0; w < 8; w++) S += red[w];
        g_M[b]    = M;
        g_invS[b] = 1.f / S;
    }
}

// ---------------------------------------------------------------------------
// k_scale: out[b,t] = exp(e-M) * invS * hsum. Fully parallel:
// 128 blocks x 256 threads, one float4 per thread (2 blocks per b).
// ---------------------------------------------------------------------------
__global__ void k_scale(float* __restrict__ out) {
    const int b   = blockIdx.x >> 1;
    const int idx = blockIdx.x * 256 + threadIdx.x;   // float4 index
    const float M   = g_M[b];
    const float inv = g_invS[b];

    const float4 e  = ((const float4*)g_e)[idx];
    const float4 hs = ((const float4*)g_hsum)[idx];
    float4 o;
    o.x = __expf(e.x - M) * inv * hs.x;
    o.y = __expf(e.y - M) * inv * hs.y;
    o.z = __expf(e.z - M) * inv * hs.z;
    o.w = __expf(e.w - M) * inv * hs.w;
    ((float4*)out)[idx] = o;
}

// ---------------------------------------------------------------------------
extern "C" void kernel_launch(void* const* d_in, const int* in_sizes, int n_in,
                              void* d_out, int out_size) {
    const float* s     = (const float*)d_in[0];   // [64, 512]
    const float* h     = (const float*)d_in[1];   // [64, 2048, 512]
    const float* phi_w = (const float*)d_in[2];   // [512, 512]
    const float* phi_b = (const float*)d_in[3];   // [512]
    const float* psi_w = (const float*)d_in[4];   // [512, 512]
    // d_in[5] = psi_b: unused (softmax shift invariance)
    float* out = (float*)d_out;                   // [64, 2048] fp32

    k_phis<<<dim3(32, 64), 256>>>(s, phi_w, phi_b);
    k_v<<<dim3(32, 4), 512>>>(psi_w);
    k_scores<<<1024, 256>>>(h);
    k_red<<<64, 256>>>();
    k_scale<<<128, 256>>>(out);
}

// round 6
// speedup vs baseline: 1.0873x; 1.0873x over previous
#include <cuda_runtime.h>

#define BB 64
#define TT 2048
#define DD 512

// Scratch (allocation-free contract: __device__ globals)
__device__ float g_phis[BB * DD];
__device__ float g_v[BB * DD];
__device__ float g_e[BB * TT];
__device__ float g_hsum[BB * TT];

// ---------------------------------------------------------------------------
// k_phis: phi_s[b,a] = dot(s[b,:], phi_w[a,:]) + phi_b[a]
// grid (32 a-tiles, 64 b) = 2048 blocks x 256 threads. Each warp does 2 a's.
// ---------------------------------------------------------------------------
__global__ void k_phis(const float* __restrict__ s,
                       const float* __restrict__ phi_w,
                       const float* __restrict__ phi_b) {
    const int b    = blockIdx.y;
    const int tid  = threadIdx.x;          // 256
    const int lane = tid & 31;
    const int warp = tid >> 5;             // 8 warps

    __shared__ float sh_s[DD];
    sh_s[tid]       = s[(size_t)b * DD + tid];
    sh_s[tid + 256] = s[(size_t)b * DD + tid + 256];
    __syncthreads();
    const float4* s4 = (const float4*)sh_s;

    const int a0 = blockIdx.x * 16 + warp * 2;
    const int a1 = a0 + 1;
    const float4* w0 = (const float4*)(phi_w + (size_t)a0 * DD);
    const float4* w1 = (const float4*)(phi_w + (size_t)a1 * DD);

    float acc0 = 0.f, acc1 = 0.f;
    #pragma unroll
    for (int j = 0; j < 4; j++) {
        float4 wa = w0[lane + 32 * j];
        float4 wb = w1[lane + 32 * j];
        float4 sv = s4[lane + 32 * j];
        acc0 += wa.x * sv.x + wa.y * sv.y + wa.z * sv.z + wa.w * sv.w;
        acc1 += wb.x * sv.x + wb.y * sv.y + wb.z * sv.z + wb.w * sv.w;
    }
    #pragma unroll
    for (int off = 16; off; off >>= 1) {
        acc0 += __shfl_xor_sync(0xffffffffu, acc0, off);
        acc1 += __shfl_xor_sync(0xffffffffu, acc1, off);
    }
    if (lane == 0) {
        g_phis[b * DD + a0] = acc0 + phi_b[a0];
        g_phis[b * DD + a1] = acc1 + phi_b[a1];
    }
}

// ---------------------------------------------------------------------------
// k_v: v[b,k] = sum_a phi_s[b,a] * psi_w[a,k]
// grid (32 b-pairs, 4 k-slices) = 128 blocks x 512 threads (16 warps).
// psi_b dropped: softmax is shift-invariant to the per-b constant it adds.
// ---------------------------------------------------------------------------
__global__ void k_v(const float* __restrict__ psi_w) {
    const int b0   = blockIdx.x * 2;
    const int ks   = blockIdx.y;           // k-slice: 32 float4 columns
    const int tid  = threadIdx.x;          // 512
    const int lane = tid & 31;
    const int warp = tid >> 5;             // 16 warps

    __shared__ float  ph0[DD], ph1[DD];
    __shared__ float4 part0[16][32];
    __shared__ float4 part1[16][32];

    ph0[tid] = g_phis[(size_t)b0 * DD + tid];
    ph1[tid] = g_phis[(size_t)(b0 + 1) * DD + tid];
    __syncthreads();

    const float4* w4 = (const float4*)psi_w;     // [512][128] float4
    const int col = ks * 32 + lane;              // 0..127

    float4 acc0 = make_float4(0.f, 0.f, 0.f, 0.f);
    float4 acc1 = make_float4(0.f, 0.f, 0.f, 0.f);
    const int abase = warp * 32;
    #pragma unroll 8
    for (int i = 0; i < 32; i++) {
        const int a = abase + i;
        const float4 w = w4[(size_t)a * 128 + col];
        const float p0 = ph0[a], p1 = ph1[a];
        acc0.x += p0 * w.x; acc0.y += p0 * w.y;
        acc0.z += p0 * w.z; acc0.w += p0 * w.w;
        acc1.x += p1 * w.x; acc1.y += p1 * w.y;
        acc1.z += p1 * w.z; acc1.w += p1 * w.w;
    }
    part0[warp][lane] = acc0;
    part1[warp][lane] = acc1;
    __syncthreads();

    if (warp == 0) {
        float4 r = part0[0][lane];
        #pragma unroll
        for (int w = 1; w < 16; w++) {
            float4 p = part0[w][lane];
            r.x += p.x; r.y += p.y; r.z += p.z; r.w += p.w;
        }
        ((float4*)g_v)[(size_t)b0 * 128 + col] = r;
    } else if (warp == 1) {
        float4 r = part1[0][lane];
        #pragma unroll
        for (int w = 1; w < 16; w++) {
            float4 p = part1[w][lane];
            r.x += p.x; r.y += p.y; r.z += p.z; r.w += p.w;
        }
        ((float4*)g_v)[(size_t)(b0 + 1) * 128 + col] = r;
    }
}

// ---------------------------------------------------------------------------
// k_scores: THE DRAM-bound pass (one 268 MB streaming read of h).
// ROUND-3 PROVEN SHAPE (fastest measured variant, ~37us): 4096 one-shot
// blocks x 256 threads; each warp: v pinned in 16 regs (loaded once),
// 4 rows in two 2-row load batches (8 in-flight LDG.128/lane, 48 data regs,
// NO launch_bounds -- register headroom matters more than occupancy cap).
// 2048 % 32 == 0 so blocks never straddle a b boundary.
// ---------------------------------------------------------------------------
__global__ void k_scores(const float* __restrict__ h) {
    const int lane = threadIdx.x & 31;
    const int warp = threadIdx.x >> 5;
    const int row0 = blockIdx.x * 32 + warp * 4;
    const int b    = row0 >> 11;           // row / 2048

    const float4* v4 = (const float4*)(g_v + (size_t)b * DD);
    float4 v[4];
    #pragma unroll
    for (int j = 0; j < 4; j++) v[j] = v4[lane + 32 * j];

    #pragma unroll
    for (int r = 0; r < 4; r += 2) {
        const float4* ha = (const float4*)(h + (size_t)(row0 + r)     * DD);
        const float4* hb = (const float4*)(h + (size_t)(row0 + r + 1) * DD);
        float4 A[4], B[4];
        #pragma unroll
        for (int j = 0; j < 4; j++) A[j] = ha[lane + 32 * j];
        #pragma unroll
        for (int j = 0; j < 4; j++) B[j] = hb[lane + 32 * j];

        float e0 = 0.f, s0 = 0.f, e1 = 0.f, s1 = 0.f;
        #pragma unroll
        for (int j = 0; j < 4; j++) {
            e0 += A[j].x * v[j].x + A[j].y * v[j].y + A[j].z * v[j].z + A[j].w * v[j].w;
            s0 += (A[j].x + A[j].y) + (A[j].z + A[j].w);
            e1 += B[j].x * v[j].x + B[j].y * v[j].y + B[j].z * v[j].z + B[j].w * v[j].w;
            s1 += (B[j].x + B[j].y) + (B[j].z + B[j].w);
        }
        #pragma unroll
        for (int off = 16; off; off >>= 1) {
            e0 += __shfl_xor_sync(0xffffffffu, e0, off);
            s0 += __shfl_xor_sync(0xffffffffu, s0, off);
            e1 += __shfl_xor_sync(0xffffffffu, e1, off);
            s1 += __shfl_xor_sync(0xffffffffu, s1, off);
        }
        if (lane == 0) {
            *(float2*)(g_e    + row0 + r) = make_float2(e0, e1);
            *(float2*)(g_hsum + row0 + r) = make_float2(s0, s1);
        }
    }
}

// ---------------------------------------------------------------------------
// k_softmax: per-b softmax over T=2048 + output c = alpha * hsum.
// 64 blocks x 512 threads, float4 everywhere, __expf, one smem reduce array.
// ---------------------------------------------------------------------------
__global__ void k_softmax(float* __restrict__ out) {
    const int b    = blockIdx.x;
    const int tid  = threadIdx.x;          // 512 -> 4 elems/thread
    const int lane = tid & 31;
    const int warp = tid >> 5;             // 16 warps
    __shared__ float red[16];

    const float4 e = ((const float4*)(g_e + (size_t)b * TT))[tid];

    float m = fmaxf(fmaxf(e.x, e.y), fmaxf(e.z, e.w));
    #pragma unroll
    for (int off = 16; off; off >>= 1)
        m = fmaxf(m, __shfl_xor_sync(0xffffffffu, m, off));
    if (lane == 0) red[warp] = m;
    __syncthreads();
    float M = red[0];
    #pragma unroll
    for (int w = 1; w < 16; w++) M = fmaxf(M, red[w]);
    __syncthreads();

    float4 ex;
    ex.x = __expf(e.x - M); ex.y = __expf(e.y - M);
    ex.z = __expf(e.z - M); ex.w = __expf(e.w - M);
    float sum = (ex.x + ex.y) + (ex.z + ex.w);
    #pragma unroll
    for (int off = 16; off; off >>= 1)
        sum += __shfl_xor_sync(0xffffffffu, sum, off);
    if (lane == 0) red[warp] = sum;
    __syncthreads();
    float S = 0.f;
    #pragma unroll
    for (int w = 0; w < 16; w++) S += red[w];
    const float inv = 1.f / S;

    const float4 hs = ((const float4*)(g_hsum + (size_t)b * TT))[tid];
    float4 o;
    o.x = ex.x * inv * hs.x; o.y = ex.y * inv * hs.y;
    o.z = ex.z * inv * hs.z; o.w = ex.w * inv * hs.w;
    ((float4*)(out + (size_t)b * TT))[tid] = o;
}

// ---------------------------------------------------------------------------
extern "C" void kernel_launch(void* const* d_in, const int* in_sizes, int n_in,
                              void* d_out, int out_size) {
    const float* s     = (const float*)d_in[0];   // [64, 512]
    const float* h     = (const float*)d_in[1];   // [64, 2048, 512]
    const float* phi_w = (const float*)d_in[2];   // [512, 512]
    const float* phi_b = (const float*)d_in[3];   // [512]
    const float* psi_w = (const float*)d_in[4];   // [512, 512]
    // d_in[5] = psi_b: unused (softmax shift invariance)
    float* out = (float*)d_out;                   // [64, 2048] fp32

    k_phis<<<dim3(32, 64), 256>>>(s, phi_w, phi_b);
    k_v<<<dim3(32, 4), 512>>>(psi_w);
    k_scores<<<4096, 256>>>(h);
    k_softmax<<<64, 512>>>(out);
}

// round 7
// speedup vs baseline: 1.1576x; 1.0646x over previous
#include <cuda_runtime.h>

#define BB 64
#define TT 2048
#define DD 512

// Scratch (allocation-free contract: __device__ globals)
__device__ float g_phis[BB * DD];
__device__ float g_v[BB * DD];
__device__ float g_e[BB * TT];
__device__ float g_hsum[BB * TT];

// ---------------------------------------------------------------------------
// k_phis: phi_s[b,a] = dot(s[b,:], phi_w[a,:]) + phi_b[a]
// grid (32 a-tiles, 64 b) = 2048 blocks x 256 threads. Each warp does 2 a's.
// ---------------------------------------------------------------------------
__global__ void k_phis(const float* __restrict__ s,
                       const float* __restrict__ phi_w,
                       const float* __restrict__ phi_b) {
    const int b    = blockIdx.y;
    const int tid  = threadIdx.x;          // 256
    const int lane = tid & 31;
    const int warp = tid >> 5;             // 8 warps

    __shared__ float sh_s[DD];
    sh_s[tid]       = s[(size_t)b * DD + tid];
    sh_s[tid + 256] = s[(size_t)b * DD + tid + 256];
    __syncthreads();
    const float4* s4 = (const float4*)sh_s;

    const int a0 = blockIdx.x * 16 + warp * 2;
    const int a1 = a0 + 1;
    const float4* w0 = (const float4*)(phi_w + (size_t)a0 * DD);
    const float4* w1 = (const float4*)(phi_w + (size_t)a1 * DD);

    float acc0 = 0.f, acc1 = 0.f;
    #pragma unroll
    for (int j = 0; j < 4; j++) {
        float4 wa = w0[lane + 32 * j];
        float4 wb = w1[lane + 32 * j];
        float4 sv = s4[lane + 32 * j];
        acc0 += wa.x * sv.x + wa.y * sv.y + wa.z * sv.z + wa.w * sv.w;
        acc1 += wb.x * sv.x + wb.y * sv.y + wb.z * sv.z + wb.w * sv.w;
    }
    #pragma unroll
    for (int off = 16; off; off >>= 1) {
        acc0 += __shfl_xor_sync(0xffffffffu, acc0, off);
        acc1 += __shfl_xor_sync(0xffffffffu, acc1, off);
    }
    if (lane == 0) {
        g_phis[b * DD + a0] = acc0 + phi_b[a0];
        g_phis[b * DD + a1] = acc1 + phi_b[a1];
    }
}

// ---------------------------------------------------------------------------
// k_v: v[b,k] = sum_a phi_s[b,a] * psi_w[a,k]
// grid (32 b-pairs, 4 k-slices) = 128 blocks x 512 threads (16 warps).
// psi_b dropped: softmax is shift-invariant to the per-b constant it adds.
// ---------------------------------------------------------------------------
__global__ void k_v(const float* __restrict__ psi_w) {
    const int b0   = blockIdx.x * 2;
    const int ks   = blockIdx.y;           // k-slice: 32 float4 columns
    const int tid  = threadIdx.x;          // 512
    const int lane = tid & 31;
    const int warp = tid >> 5;             // 16 warps

    __shared__ float  ph0[DD], ph1[DD];
    __shared__ float4 part0[16][32];
    __shared__ float4 part1[16][32];

    ph0[tid] = g_phis[(size_t)b0 * DD + tid];
    ph1[tid] = g_phis[(size_t)(b0 + 1) * DD + tid];
    __syncthreads();

    const float4* w4 = (const float4*)psi_w;     // [512][128] float4
    const int col = ks * 32 + lane;              // 0..127

    float4 acc0 = make_float4(0.f, 0.f, 0.f, 0.f);
    float4 acc1 = make_float4(0.f, 0.f, 0.f, 0.f);
    const int abase = warp * 32;
    #pragma unroll 8
    for (int i = 0; i < 32; i++) {
        const int a = abase + i;
        const float4 w = w4[(size_t)a * 128 + col];
        const float p0 = ph0[a], p1 = ph1[a];
        acc0.x += p0 * w.x; acc0.y += p0 * w.y;
        acc0.z += p0 * w.z; acc0.w += p0 * w.w;
        acc1.x += p1 * w.x; acc1.y += p1 * w.y;
        acc1.z += p1 * w.z; acc1.w += p1 * w.w;
    }
    part0[warp][lane] = acc0;
    part1[warp][lane] = acc1;
    __syncthreads();

    if (warp == 0) {
        float4 r = part0[0][lane];
        #pragma unroll
        for (int w = 1; w < 16; w++) {
            float4 p = part0[w][lane];
            r.x += p.x; r.y += p.y; r.z += p.z; r.w += p.w;
        }
        ((float4*)g_v)[(size_t)b0 * 128 + col] = r;
    } else if (warp == 1) {
        float4 r = part1[0][lane];
        #pragma unroll
        for (int w = 1; w < 16; w++) {
            float4 p = part1[w][lane];
            r.x += p.x; r.y += p.y; r.z += p.z; r.w += p.w;
        }
        ((float4*)g_v)[(size_t)(b0 + 1) * 128 + col] = r;
    }
}

// ---------------------------------------------------------------------------
// k_scores v3: the DRAM-bound pass (one 268 MB streaming read of h).
// grid 8192 x 256, __launch_bounds__(256,4): ~60 live regs -> 4 CTAs/SM
// = 32 warps/SM, doubling in-flight load bytes vs the 2-CTA variants.
// v staged via smem ONCE per block (no per-warp L2 v-traffic), then pinned
// in 16 regs per warp. Each warp: 2 rows, 8 independent LDG.128/lane.
// 16 rows/block; 2048 % 16 == 0 so blocks never straddle a b boundary.
// ---------------------------------------------------------------------------
__global__ void __launch_bounds__(256, 4) k_scores(const float* __restrict__ h) {
    const int tid  = threadIdx.x;
    const int lane = tid & 31;
    const int warp = tid >> 5;
    const int row0 = blockIdx.x * 16 + warp * 2;
    const int b    = blockIdx.x >> 7;      // 128 blocks per b

    __shared__ float sh_v[DD];
    ((float2*)sh_v)[tid] = ((const float2*)(g_v + (size_t)b * DD))[tid];
    __syncthreads();

    const float4* sv4 = (const float4*)sh_v;
    float4 v[4];
    #pragma unroll
    for (int j = 0; j < 4; j++) v[j] = sv4[lane + 32 * j];

    const float4* ha = (const float4*)(h + (size_t)row0 * DD);
    const float4* hb = ha + 128;
    float4 A[4], B[4];
    #pragma unroll
    for (int j = 0; j < 4; j++) A[j] = ha[lane + 32 * j];
    #pragma unroll
    for (int j = 0; j < 4; j++) B[j] = hb[lane + 32 * j];

    float e0 = 0.f, s0 = 0.f, e1 = 0.f, s1 = 0.f;
    #pragma unroll
    for (int j = 0; j < 4; j++) {
        e0 += A[j].x * v[j].x + A[j].y * v[j].y + A[j].z * v[j].z + A[j].w * v[j].w;
        s0 += (A[j].x + A[j].y) + (A[j].z + A[j].w);
        e1 += B[j].x * v[j].x + B[j].y * v[j].y + B[j].z * v[j].z + B[j].w * v[j].w;
        s1 += (B[j].x + B[j].y) + (B[j].z + B[j].w);
    }
    #pragma unroll
    for (int off = 16; off; off >>= 1) {
        e0 += __shfl_xor_sync(0xffffffffu, e0, off);
        s0 += __shfl_xor_sync(0xffffffffu, s0, off);
        e1 += __shfl_xor_sync(0xffffffffu, e1, off);
        s1 += __shfl_xor_sync(0xffffffffu, s1, off);
    }
    if (lane == 0) {
        *(float2*)(g_e    + row0) = make_float2(e0, e1);
        *(float2*)(g_hsum + row0) = make_float2(s0, s1);
    }
}

// ---------------------------------------------------------------------------
// k_softmax: per-b softmax over T=2048 + output c = alpha * hsum.
// 64 blocks x 1024 threads (2 e/thread). hsum loaded up front so its
// latency overlaps both block reductions.
// ---------------------------------------------------------------------------
__global__ void k_softmax(float* __restrict__ out) {
    const int b    = blockIdx.x;
    const int tid  = threadIdx.x;          // 1024 -> 2 elems/thread
    const int lane = tid & 31;
    const int warp = tid >> 5;             // 32 warps
    __shared__ float red[32];

    const float2 e  = ((const float2*)(g_e    + (size_t)b * TT))[tid];
    const float2 hs = ((const float2*)(g_hsum + (size_t)b * TT))[tid];

    float m = fmaxf(e.x, e.y);
    #pragma unroll
    for (int off = 16; off; off >>= 1)
        m = fmaxf(m, __shfl_xor_sync(0xffffffffu, m, off));
    if (lane == 0) red[warp] = m;
    __syncthreads();
    float M = red[0];
    #pragma unroll
    for (int w = 1; w < 32; w++) M = fmaxf(M, red[w]);
    __syncthreads();

    const float ex0 = __expf(e.x - M);
    const float ex1 = __expf(e.y - M);
    float sum = ex0 + ex1;
    #pragma unroll
    for (int off = 16; off; off >>= 1)
        sum += __shfl_xor_sync(0xffffffffu, sum, off);
    if (lane == 0) red[warp] = sum;
    __syncthreads();
    float S = 0.f;
    #pragma unroll
    for (int w = 0; w < 32; w++) S += red[w];
    const float inv = 1.f / S;

    float2 o;
    o.x = ex0 * inv * hs.x;
    o.y = ex1 * inv * hs.y;
    ((float2*)(out + (size_t)b * TT))[tid] = o;
}

// ---------------------------------------------------------------------------
extern "C" void kernel_launch(void* const* d_in, const int* in_sizes, int n_in,
                              void* d_out, int out_size) {
    const float* s     = (const float*)d_in[0];   // [64, 512]
    const float* h     = (const float*)d_in[1];   // [64, 2048, 512]
    const float* phi_w = (const float*)d_in[2];   // [512, 512]
    const float* phi_b = (const float*)d_in[3];   // [512]
    const float* psi_w = (const float*)d_in[4];   // [512, 512]
    // d_in[5] = psi_b: unused (softmax shift invariance)
    float* out = (float*)d_out;                   // [64, 2048] fp32

    k_phis<<<dim3(32, 64), 256>>>(s, phi_w, phi_b);
    k_v<<<dim3(32, 4), 512>>>(psi_w);
    k_scores<<<8192, 256>>>(h);    // 8192 * 16 rows = 131072 = BB*TT
    k_softmax<<<64, 1024>>>(out);
}